// round 1
// baseline (speedup 1.0000x reference)
#include <cuda_runtime.h>

#define NN 100000
#define NE 1600000
#define ET (NE + NN)      // edges incl. self loops = 1700000
#define F  64
#define NFI 128
#define NLAY 4

// ---------------- device scratch (static globals; no runtime alloc) ----------
__device__ float d_x[NN * F];      // node state
__device__ float d_g[NN * F];      // per-layer linear output
__device__ float d_h[NN * F];      // running h accumulator
__device__ float d_e[ET];          // per-edge logits -> exp values
__device__ int   d_deg[NN];
__device__ int   d_off[NN + 1];
__device__ int   d_cur[NN];
__device__ int   d_ssrc[ET];       // src node per sorted edge slot
__device__ int   d_seid[ET];       // original edge id per sorted slot
__device__ float d_sum[F];
__device__ float d_sumsq[F];
__device__ float d_scale[F];
__device__ float d_shift[F];

__device__ __forceinline__ float lrelu(float v, float s) { return v > 0.f ? v : s * v; }

// ---------------- init: deg=1 (self loop), cur=0 ----------------------------
__global__ void k_init() {
    int i = blockIdx.x * blockDim.x + threadIdx.x;
    if (i < NN) { d_deg[i] = 1; d_cur[i] = 0; }
}

// ---------------- histogram of dst -------------------------------------------
__global__ void k_hist(const int* __restrict__ ei) {
    int e = blockIdx.x * blockDim.x + threadIdx.x;
    if (e < NE) atomicAdd(&d_deg[ei[NE + e]], 1);
}

// ---------------- single-block exclusive scan of deg -> off ------------------
__global__ void k_scan() {
    __shared__ int warpsum[32];
    __shared__ int carry_s;
    int tid = threadIdx.x, lane = tid & 31, wid = tid >> 5;
    if (tid == 0) carry_s = 0;
    __syncthreads();
    for (int base = 0; base < NN; base += 1024) {
        int i = base + tid;
        int v = (i < NN) ? d_deg[i] : 0;
        int x = v;
        #pragma unroll
        for (int o = 1; o < 32; o <<= 1) {
            int t = __shfl_up_sync(0xFFFFFFFFu, x, o);
            if (lane >= o) x += t;
        }
        if (lane == 31) warpsum[wid] = x;
        __syncthreads();
        if (wid == 0) {
            int s = warpsum[lane];
            #pragma unroll
            for (int o = 1; o < 32; o <<= 1) {
                int t = __shfl_up_sync(0xFFFFFFFFu, s, o);
                if (lane >= o) s += t;
            }
            warpsum[lane] = s;
        }
        __syncthreads();
        int pre = (wid == 0) ? 0 : warpsum[wid - 1];
        int incl = x + pre;
        if (i < NN) d_off[i] = carry_s + incl - v;
        __syncthreads();
        if (tid == 1023) carry_s += incl;
        __syncthreads();
    }
    if (threadIdx.x == 0) d_off[NN] = carry_s;
}

// ---------------- scatter edges into CSR slots -------------------------------
__global__ void k_scatter(const int* __restrict__ ei) {
    int idx = blockIdx.x * blockDim.x + threadIdx.x;
    if (idx >= ET) return;
    int s, d;
    if (idx < NE) { s = ei[idx]; d = ei[NE + idx]; }
    else          { s = idx - NE; d = s; }
    int p = d_off[d] + atomicAdd(&d_cur[d], 1);
    d_ssrc[p] = s;
    d_seid[p] = idx;
}

// ---------------- encoder: x = lrelu(concat(xf, emb[id]) @ Win + bin) --------
// block = 256 threads, 16 nodes/block. smem: W 32KB + Xin 8KB
__global__ void k_enc(const float* __restrict__ xf, const int* __restrict__ ids,
                      const float* __restrict__ emb, const float* __restrict__ w,
                      const float* __restrict__ b) {
    __shared__ float Wsm[NFI * F];
    __shared__ float Xin[16 * NFI];
    int tid = threadIdx.x;
    for (int k = tid; k < NFI * F; k += 256) Wsm[k] = w[k];
    int node0 = blockIdx.x * 16;
    for (int k = tid; k < 16 * NFI; k += 256) {
        int nl = k >> 7, kk = k & 127;
        int node = node0 + nl;
        float v = 0.f;
        if (node < NN) {
            if (kk < 124) v = xf[node * 124 + kk];
            else          v = emb[ids[node] * 4 + (kk - 124)];
        }
        Xin[k] = v;
    }
    __syncthreads();
    int f = tid & 63, g = tid >> 6;
    float bb = b[f];
    for (int nl = g; nl < 16; nl += 4) {
        int node = node0 + nl;
        if (node >= NN) break;
        float acc = bb;
        const float* xr = &Xin[nl * NFI];
        #pragma unroll 16
        for (int k = 0; k < NFI; k++) acc += xr[k] * Wsm[k * F + f];
        d_x[node * F + f] = lrelu(acc, 0.01f);
    }
}

// ---------------- per-layer linear: g = x @ W + b ----------------------------
// block = 256, 64 nodes/block. smem: W 16KB + Xin 16KB
__global__ void k_lin(const float* __restrict__ w, const float* __restrict__ b) {
    __shared__ float Wsm[F * F];
    __shared__ float Xin[64 * F];
    int tid = threadIdx.x;
    for (int k = tid; k < F * F; k += 256) Wsm[k] = w[k];
    int node0 = blockIdx.x * 64;
    for (int k = tid; k < 64 * F; k += 256) {
        int nl = k >> 6, kk = k & 63;
        int node = node0 + nl;
        Xin[k] = (node < NN) ? d_x[node * F + kk] : 0.f;
    }
    __syncthreads();
    int f = tid & 63, g = tid >> 6;
    float bb = b[f];
    for (int nl = g; nl < 64; nl += 4) {
        int node = node0 + nl;
        if (node >= NN) break;
        float acc = bb;
        const float* xr = &Xin[nl * F];
        #pragma unroll
        for (int k = 0; k < F; k++) acc += xr[k] * Wsm[k * F + f];
        d_g[node * F + f] = acc;
    }
}

// ---------------- fused GATv2 edge phase: one warp per dst node --------------
// logits -> segment max -> exp/sum -> alpha (write to xs) -> weighted agg
__global__ void k_gat(const float* __restrict__ att, const float* __restrict__ cb,
                      float* __restrict__ xs_out) {
    int w = (blockIdx.x * blockDim.x + threadIdx.x) >> 5;
    int lane = threadIdx.x & 31;
    if (w >= NN) return;
    int beg = d_off[w], end = d_off[w + 1];

    float a0 = att[lane], a1 = att[32 + lane];
    float gd0 = d_g[w * F + lane], gd1 = d_g[w * F + 32 + lane];

    // pass 1: logits + running max
    float m = -1e30f;
    for (int p = beg; p < end; ++p) {
        int s = d_ssrc[p];
        float t = lrelu(d_g[s * F + lane] + gd0, 0.2f) * a0
                + lrelu(d_g[s * F + 32 + lane] + gd1, 0.2f) * a1;
        #pragma unroll
        for (int o = 16; o > 0; o >>= 1) t += __shfl_xor_sync(0xFFFFFFFFu, t, o);
        if (lane == 0) d_e[p] = t;
        m = fmaxf(m, t);
    }
    __syncwarp();

    // pass 2: exp + sum (lanes stride over edges)
    float ssum = 0.f;
    for (int p = beg + lane; p < end; p += 32) {
        float ee = __expf(d_e[p] - m);
        d_e[p] = ee;
        ssum += ee;
    }
    #pragma unroll
    for (int o = 16; o > 0; o >>= 1) ssum += __shfl_xor_sync(0xFFFFFFFFu, ssum, o);
    float inv = 1.f / ssum;
    __syncwarp();

    // pass 3: alpha write + weighted aggregation
    float acc0 = 0.f, acc1 = 0.f;
    for (int p = beg; p < end; ++p) {
        float alpha = d_e[p] * inv;
        int s = d_ssrc[p];
        acc0 += alpha * d_g[s * F + lane];
        acc1 += alpha * d_g[s * F + 32 + lane];
        if (lane == 0) xs_out[d_seid[p]] = alpha;
    }
    d_x[w * F + lane]      = acc0 + cb[lane];
    d_x[w * F + 32 + lane] = acc1 + cb[32 + lane];
}

// ---------------- GraphNorm reductions ---------------------------------------
__global__ void k_zero_sums() {
    int t = threadIdx.x;
    if (t < F) { d_sum[t] = 0.f; d_sumsq[t] = 0.f; }
}

__global__ void k_red() {
    int f = threadIdx.x & 63, grp = threadIdx.x >> 6;
    float s = 0.f, s2 = 0.f;
    for (int i = blockIdx.x * 4 + grp; i < NN; i += gridDim.x * 4) {
        float v = d_x[i * F + f];
        s += v; s2 += v * v;
    }
    __shared__ float sm[256], sm2[256];
    sm[threadIdx.x] = s; sm2[threadIdx.x] = s2;
    __syncthreads();
    if (grp == 0) {
        s  = sm[f]  + sm[64 + f]  + sm[128 + f]  + sm[192 + f];
        s2 = sm2[f] + sm2[64 + f] + sm2[128 + f] + sm2[192 + f];
        atomicAdd(&d_sum[f], s);
        atomicAdd(&d_sumsq[f], s2);
    }
}

__global__ void k_stats(const float* __restrict__ gw, const float* __restrict__ gb,
                        const float* __restrict__ gms) {
    int f = threadIdx.x;
    if (f >= F) return;
    const float invn = 1.f / (float)NN;
    float mean = d_sum[f] * invn;
    float ex2  = d_sumsq[f] * invn;
    float mm   = mean * gms[f];
    float var  = ex2 - 2.f * mm * mean + mm * mm;
    float inv  = rsqrtf(var + 1e-5f);
    float sc   = inv * gw[f];
    d_scale[f] = sc;
    d_shift[f] = gb[f] - mm * sc;
}

__global__ void k_norm(int first) {
    int total = NN * F;
    for (int i = blockIdx.x * blockDim.x + threadIdx.x; i < total;
         i += gridDim.x * blockDim.x) {
        int f = i & 63;
        float v = d_x[i] * d_scale[f] + d_shift[f];
        v = lrelu(v, 0.01f);
        d_x[i] = v;
        d_h[i] = first ? 0.5f * v : d_h[i] + 0.5f * v;
    }
}

// ---------------- final output copy ------------------------------------------
__global__ void k_out(float* __restrict__ out) {
    int total = NN * F;
    for (int i = blockIdx.x * blockDim.x + threadIdx.x; i < total;
         i += gridDim.x * blockDim.x) {
        out[i] = d_x[i];
        out[total + i] = d_h[i];
    }
}

// ---------------- launch ------------------------------------------------------
extern "C" void kernel_launch(void* const* d_in, const int* in_sizes, int n_in,
                              void* d_out, int out_size) {
    const float* x_feat   = (const float*)d_in[0];
    const int*   node_ids = (const int*)  d_in[1];
    const int*   edge_idx = (const int*)  d_in[2];
    const float* emb      = (const float*)d_in[3];
    const float* w_in     = (const float*)d_in[4];
    const float* b_in     = (const float*)d_in[5];
    const float* lin_w    = (const float*)d_in[6];
    const float* lin_b    = (const float*)d_in[7];
    const float* att      = (const float*)d_in[8];
    const float* conv_b   = (const float*)d_in[9];
    const float* gn_w     = (const float*)d_in[10];
    const float* gn_b     = (const float*)d_in[11];
    const float* gn_ms    = (const float*)d_in[12];
    float* out = (float*)d_out;

    // preprocessing: CSR by dst (incl. self loops)
    k_init<<<(NN + 255) / 256, 256>>>();
    k_hist<<<(NE + 255) / 256, 256>>>(edge_idx);
    k_scan<<<1, 1024>>>();
    k_scatter<<<(ET + 255) / 256, 256>>>(edge_idx);

    // encoder
    k_enc<<<(NN + 15) / 16, 256>>>(x_feat, node_ids, emb, w_in, b_in);

    for (int l = 0; l < NLAY; l++) {
        k_lin<<<(NN + 63) / 64, 256>>>(lin_w + l * F * F, lin_b + l * F);
        k_gat<<<(NN + 7) / 8, 256>>>(att + l * F, conv_b + l * F,
                                     out + 2 * NN * F + (size_t)l * ET);
        k_zero_sums<<<1, 64>>>();
        k_red<<<592, 256>>>();
        k_stats<<<1, 64>>>(gn_w + l * F, gn_b + l * F, gn_ms + l * F);
        k_norm<<<2048, 256>>>(l == 0 ? 1 : 0);
    }

    k_out<<<(NN * F + 255) / 256, 256>>>(out);
    (void)in_sizes; (void)n_in; (void)out_size;
}

// round 2
// speedup vs baseline: 1.1736x; 1.1736x over previous
#include <cuda_runtime.h>

#define NN 100000
#define NE 1600000
#define ET (NE + NN)      // edges incl. self loops = 1700000
#define F  64
#define NFI 128
#define NLAY 4

// ---------------- device scratch (static globals; no runtime alloc) ----------
__device__ float d_x[NN * F];      // node state
__device__ float d_g[NN * F];      // per-layer linear output
__device__ float d_h[NN * F];      // running h accumulator
__device__ float d_e[ET];          // per-edge raw logits
__device__ int   d_deg[NN];
__device__ int   d_off[NN + 1];
__device__ int   d_cur[NN];
__device__ int   d_ssrc[ET];       // src node per sorted edge slot
__device__ int   d_seid[ET];       // original edge id per sorted slot
__device__ float d_sum[F];
__device__ float d_sumsq[F];
__device__ float d_scale[F];
__device__ float d_shift[F];

__device__ __forceinline__ float lrelu(float v, float s) { return v > 0.f ? v : s * v; }

// ---------------- init: deg=1 (self loop), cur=0 ----------------------------
__global__ void k_init() {
    int i = blockIdx.x * blockDim.x + threadIdx.x;
    if (i < NN) { d_deg[i] = 1; d_cur[i] = 0; }
}

// ---------------- histogram of dst -------------------------------------------
__global__ void k_hist(const int* __restrict__ ei) {
    int e = blockIdx.x * blockDim.x + threadIdx.x;
    if (e < NE) atomicAdd(&d_deg[ei[NE + e]], 1);
}

// ---------------- single-block exclusive scan of deg -> off ------------------
__global__ void k_scan() {
    __shared__ int warpsum[32];
    __shared__ int carry_s;
    int tid = threadIdx.x, lane = tid & 31, wid = tid >> 5;
    if (tid == 0) carry_s = 0;
    __syncthreads();
    for (int base = 0; base < NN; base += 1024) {
        int i = base + tid;
        int v = (i < NN) ? d_deg[i] : 0;
        int x = v;
        #pragma unroll
        for (int o = 1; o < 32; o <<= 1) {
            int t = __shfl_up_sync(0xFFFFFFFFu, x, o);
            if (lane >= o) x += t;
        }
        if (lane == 31) warpsum[wid] = x;
        __syncthreads();
        if (wid == 0) {
            int s = warpsum[lane];
            #pragma unroll
            for (int o = 1; o < 32; o <<= 1) {
                int t = __shfl_up_sync(0xFFFFFFFFu, s, o);
                if (lane >= o) s += t;
            }
            warpsum[lane] = s;
        }
        __syncthreads();
        int pre = (wid == 0) ? 0 : warpsum[wid - 1];
        int incl = x + pre;
        if (i < NN) d_off[i] = carry_s + incl - v;
        __syncthreads();
        if (tid == 1023) carry_s += incl;
        __syncthreads();
    }
    if (threadIdx.x == 0) d_off[NN] = carry_s;
}

// ---------------- scatter edges into CSR slots -------------------------------
__global__ void k_scatter(const int* __restrict__ ei) {
    int idx = blockIdx.x * blockDim.x + threadIdx.x;
    if (idx >= ET) return;
    int s, d;
    if (idx < NE) { s = ei[idx]; d = ei[NE + idx]; }
    else          { s = idx - NE; d = s; }
    int p = d_off[d] + atomicAdd(&d_cur[d], 1);
    d_ssrc[p] = s;
    d_seid[p] = idx;
}

// ---------------- encoder: x = lrelu(concat(xf, emb[id]) @ Win + bin) --------
__global__ void k_enc(const float* __restrict__ xf, const int* __restrict__ ids,
                      const float* __restrict__ emb, const float* __restrict__ w,
                      const float* __restrict__ b) {
    __shared__ float Wsm[NFI * F];
    __shared__ float Xin[16 * NFI];
    int tid = threadIdx.x;
    for (int k = tid; k < NFI * F; k += 256) Wsm[k] = w[k];
    int node0 = blockIdx.x * 16;
    for (int k = tid; k < 16 * NFI; k += 256) {
        int nl = k >> 7, kk = k & 127;
        int node = node0 + nl;
        float v = 0.f;
        if (node < NN) {
            if (kk < 124) v = xf[node * 124 + kk];
            else          v = emb[ids[node] * 4 + (kk - 124)];
        }
        Xin[k] = v;
    }
    __syncthreads();
    int f = tid & 63, g = tid >> 6;
    float bb = b[f];
    for (int nl = g; nl < 16; nl += 4) {
        int node = node0 + nl;
        if (node >= NN) break;
        float acc = bb;
        const float* xr = &Xin[nl * NFI];
        #pragma unroll 16
        for (int k = 0; k < NFI; k++) acc += xr[k] * Wsm[k * F + f];
        d_x[node * F + f] = lrelu(acc, 0.01f);
    }
}

// ---------------- per-layer linear: g = x @ W + b ----------------------------
__global__ void k_lin(const float* __restrict__ w, const float* __restrict__ b) {
    __shared__ float Wsm[F * F];
    __shared__ float Xin[64 * F];
    int tid = threadIdx.x;
    for (int k = tid; k < F * F; k += 256) Wsm[k] = w[k];
    int node0 = blockIdx.x * 64;
    for (int k = tid; k < 64 * F; k += 256) {
        int nl = k >> 6, kk = k & 63;
        int node = node0 + nl;
        Xin[k] = (node < NN) ? d_x[node * F + kk] : 0.f;
    }
    __syncthreads();
    int f = tid & 63, g = tid >> 6;
    float bb = b[f];
    for (int nl = g; nl < 64; nl += 4) {
        int node = node0 + nl;
        if (node >= NN) break;
        float acc = bb;
        const float* xr = &Xin[nl * F];
        #pragma unroll
        for (int k = 0; k < F; k++) acc += xr[k] * Wsm[k * F + f];
        d_g[node * F + f] = acc;
    }
}

// ---------------- fused GATv2 edge phase: one warp per dst node --------------
// Online softmax: single gather of g[src]; raw logits stashed for alpha pass.
__global__ void k_gat(const float* __restrict__ att, const float* __restrict__ cb,
                      float* __restrict__ xs_out) {
    int w = (blockIdx.x * blockDim.x + threadIdx.x) >> 5;
    int lane = threadIdx.x & 31;
    if (w >= NN) return;
    int beg = d_off[w], end = d_off[w + 1];

    const float2* g2 = (const float2*)d_g;
    float2 a  = __ldg((const float2*)att + lane);
    float2 gd = __ldg(g2 + w * 32 + lane);

    float m = -1e30f;
    float ssum = 0.f;
    float acc0 = 0.f, acc1 = 0.f;

    int p = beg;
    // 2-edge unrolled online-softmax mainloop
    for (; p + 1 < end; p += 2) {
        int s0 = d_ssrc[p], s1 = d_ssrc[p + 1];
        float2 v0 = __ldg(g2 + s0 * 32 + lane);
        float2 v1 = __ldg(g2 + s1 * 32 + lane);
        float t0 = lrelu(v0.x + gd.x, 0.2f) * a.x + lrelu(v0.y + gd.y, 0.2f) * a.y;
        float t1 = lrelu(v1.x + gd.x, 0.2f) * a.x + lrelu(v1.y + gd.y, 0.2f) * a.y;
        #pragma unroll
        for (int o = 16; o > 0; o >>= 1) {
            t0 += __shfl_xor_sync(0xFFFFFFFFu, t0, o);
            t1 += __shfl_xor_sync(0xFFFFFFFFu, t1, o);
        }
        if (lane == 0) { d_e[p] = t0; d_e[p + 1] = t1; }
        // edge 0
        if (t0 > m) {
            float c = __expf(m - t0);
            ssum *= c; acc0 *= c; acc1 *= c; m = t0;
            ssum += 1.f; acc0 += v0.x; acc1 += v0.y;
        } else {
            float e0 = __expf(t0 - m);
            ssum += e0; acc0 += e0 * v0.x; acc1 += e0 * v0.y;
        }
        // edge 1
        if (t1 > m) {
            float c = __expf(m - t1);
            ssum *= c; acc0 *= c; acc1 *= c; m = t1;
            ssum += 1.f; acc0 += v1.x; acc1 += v1.y;
        } else {
            float e1 = __expf(t1 - m);
            ssum += e1; acc0 += e1 * v1.x; acc1 += e1 * v1.y;
        }
    }
    if (p < end) {
        int s0 = d_ssrc[p];
        float2 v0 = __ldg(g2 + s0 * 32 + lane);
        float t0 = lrelu(v0.x + gd.x, 0.2f) * a.x + lrelu(v0.y + gd.y, 0.2f) * a.y;
        #pragma unroll
        for (int o = 16; o > 0; o >>= 1) t0 += __shfl_xor_sync(0xFFFFFFFFu, t0, o);
        if (lane == 0) d_e[p] = t0;
        if (t0 > m) {
            float c = __expf(m - t0);
            ssum *= c; acc0 *= c; acc1 *= c; m = t0;
            ssum += 1.f; acc0 += v0.x; acc1 += v0.y;
        } else {
            float e0 = __expf(t0 - m);
            ssum += e0; acc0 += e0 * v0.x; acc1 += e0 * v0.y;
        }
    }

    float inv = 1.f / ssum;

    // alpha pass: scalar logit -> alpha, lanes stride over edges
    for (int q = beg + lane; q < end; q += 32) {
        float alpha = __expf(d_e[q] - m) * inv;
        xs_out[d_seid[q]] = alpha;
    }

    float2 cbv = __ldg((const float2*)cb + lane);
    float2 xo;
    xo.x = acc0 * inv + cbv.x;
    xo.y = acc1 * inv + cbv.y;
    ((float2*)d_x)[w * 32 + lane] = xo;
}

// ---------------- GraphNorm reductions ---------------------------------------
__global__ void k_zero_sums() {
    int t = threadIdx.x;
    if (t < F) { d_sum[t] = 0.f; d_sumsq[t] = 0.f; }
}

__global__ void k_red() {
    int f = threadIdx.x & 63, grp = threadIdx.x >> 6;
    float s = 0.f, s2 = 0.f;
    for (int i = blockIdx.x * 4 + grp; i < NN; i += gridDim.x * 4) {
        float v = d_x[i * F + f];
        s += v; s2 += v * v;
    }
    __shared__ float sm[256], sm2[256];
    sm[threadIdx.x] = s; sm2[threadIdx.x] = s2;
    __syncthreads();
    if (grp == 0) {
        s  = sm[f]  + sm[64 + f]  + sm[128 + f]  + sm[192 + f];
        s2 = sm2[f] + sm2[64 + f] + sm2[128 + f] + sm2[192 + f];
        atomicAdd(&d_sum[f], s);
        atomicAdd(&d_sumsq[f], s2);
    }
}

__global__ void k_stats(const float* __restrict__ gw, const float* __restrict__ gb,
                        const float* __restrict__ gms) {
    int f = threadIdx.x;
    if (f >= F) return;
    const float invn = 1.f / (float)NN;
    float mean = d_sum[f] * invn;
    float ex2  = d_sumsq[f] * invn;
    float mm   = mean * gms[f];
    float var  = ex2 - 2.f * mm * mean + mm * mm;
    float inv  = rsqrtf(var + 1e-5f);
    float sc   = inv * gw[f];
    d_scale[f] = sc;
    d_shift[f] = gb[f] - mm * sc;
}

// norm + activation + h-accumulate; on last layer writes outputs directly
__global__ void k_norm(int first, float* __restrict__ outx, float* __restrict__ outh) {
    int total = NN * F;
    for (int i = blockIdx.x * blockDim.x + threadIdx.x; i < total;
         i += gridDim.x * blockDim.x) {
        int f = i & 63;
        float v = d_x[i] * d_scale[f] + d_shift[f];
        v = lrelu(v, 0.01f);
        float hv = first ? 0.5f * v : d_h[i] + 0.5f * v;
        if (outx) {
            outx[i] = v;
            outh[i] = hv;
        } else {
            d_x[i] = v;
            d_h[i] = hv;
        }
    }
}

// ---------------- launch ------------------------------------------------------
extern "C" void kernel_launch(void* const* d_in, const int* in_sizes, int n_in,
                              void* d_out, int out_size) {
    const float* x_feat   = (const float*)d_in[0];
    const int*   node_ids = (const int*)  d_in[1];
    const int*   edge_idx = (const int*)  d_in[2];
    const float* emb      = (const float*)d_in[3];
    const float* w_in     = (const float*)d_in[4];
    const float* b_in     = (const float*)d_in[5];
    const float* lin_w    = (const float*)d_in[6];
    const float* lin_b    = (const float*)d_in[7];
    const float* att      = (const float*)d_in[8];
    const float* conv_b   = (const float*)d_in[9];
    const float* gn_w     = (const float*)d_in[10];
    const float* gn_b     = (const float*)d_in[11];
    const float* gn_ms    = (const float*)d_in[12];
    float* out = (float*)d_out;

    // preprocessing: CSR by dst (incl. self loops)
    k_init<<<(NN + 255) / 256, 256>>>();
    k_hist<<<(NE + 255) / 256, 256>>>(edge_idx);
    k_scan<<<1, 1024>>>();
    k_scatter<<<(ET + 255) / 256, 256>>>(edge_idx);

    // encoder
    k_enc<<<(NN + 15) / 16, 256>>>(x_feat, node_ids, emb, w_in, b_in);

    for (int l = 0; l < NLAY; l++) {
        k_lin<<<(NN + 63) / 64, 256>>>(lin_w + l * F * F, lin_b + l * F);
        k_gat<<<(NN + 7) / 8, 256>>>(att + l * F, conv_b + l * F,
                                     out + 2 * NN * F + (size_t)l * ET);
        k_zero_sums<<<1, 64>>>();
        k_red<<<592, 256>>>();
        k_stats<<<1, 64>>>(gn_w + l * F, gn_b + l * F, gn_ms + l * F);
        int last = (l == NLAY - 1);
        k_norm<<<2048, 256>>>(l == 0 ? 1 : 0,
                              last ? out : (float*)nullptr,
                              last ? out + NN * F : (float*)nullptr);
    }

    (void)in_sizes; (void)n_in; (void)out_size;
}